// round 16
// baseline (speedup 1.0000x reference)
#include <cuda_runtime.h>
#include <cuda_fp16.h>
#include <cstdint>

#define NROWS 8192
#define C     128
#define KSPLIT 8
#define KRANGE (NROWS / KSPLIT)   // 1024
#define BK 64
#define NITER (KRANGE / BK)       // 16
#define BM 64
#define THREADS 256

#define RS_A 144                  // 64 fp16 = 128B + 16B pad
#define RS_B 272                  // 128 fp16 = 256B + 16B pad
#define TILE_A  (BM * RS_A)       // 9216
#define TILE_BT (BK * RS_B)       // 17408
#define OFF_B0  (2 * TILE_A)      // 18432
#define SMEM_BYTES (OFF_B0 + 3 * TILE_BT + 128)   // ~70.8KB -> 2 CTAs/SM

// k_linear smem (64 rows per CTA)
#define LRS 272                   // 128 fp16 + 16B pad
#define L_TILE_X (64 * LRS)       // 17408
#define L_SMEM (L_TILE_X + 128 * LRS + 128)       // ~52.4KB

// ---- scratch ----
__device__ __half g_hf[NROWS * C];            // h fp16 row-major
__device__ __half g_part[KSPLIT * NROWS * C]; // fp16 partials (16 MB)

// ============================ helpers ============================
__device__ __forceinline__ uint32_t smem_u32(const void* p) {
    uint32_t a;
    asm("{ .reg .u64 t; cvta.to.shared.u64 t, %1; cvt.u32.u64 %0, t; }" : "=r"(a) : "l"(p));
    return a;
}
__device__ __forceinline__ void ldsm4(uint32_t* r, uint32_t addr) {
    asm volatile("ldmatrix.sync.aligned.m8n8.x4.shared.b16 {%0,%1,%2,%3}, [%4];"
                 : "=r"(r[0]), "=r"(r[1]), "=r"(r[2]), "=r"(r[3]) : "r"(addr));
}
__device__ __forceinline__ void ldsm2(uint32_t* r, uint32_t addr) {
    asm volatile("ldmatrix.sync.aligned.m8n8.x2.shared.b16 {%0,%1}, [%2];"
                 : "=r"(r[0]), "=r"(r[1]) : "r"(addr));
}
// x4 trans: lanes 0-15 -> k-rows of n-block0, lanes 16-31 -> k-rows of n-block1.
// Returns {b[k16,n0..7] (2 regs), b[k16,n8..15] (2 regs)}.
__device__ __forceinline__ void ldsm4t(uint32_t* r, uint32_t addr) {
    asm volatile("ldmatrix.sync.aligned.m8n8.x4.trans.shared.b16 {%0,%1,%2,%3}, [%4];"
                 : "=r"(r[0]), "=r"(r[1]), "=r"(r[2]), "=r"(r[3]) : "r"(addr));
}
__device__ __forceinline__ void mma_f16(float* d, const uint32_t* a, const uint32_t* b) {
    asm volatile(
        "mma.sync.aligned.m16n8k16.row.col.f32.f16.f16.f32 "
        "{%0,%1,%2,%3}, {%4,%5,%6,%7}, {%8,%9}, {%0,%1,%2,%3};"
        : "+f"(d[0]), "+f"(d[1]), "+f"(d[2]), "+f"(d[3])
        : "r"(a[0]), "r"(a[1]), "r"(a[2]), "r"(a[3]), "r"(b[0]), "r"(b[1]));
}
__device__ __forceinline__ void cp16(uint32_t dst, const void* src) {
    asm volatile("cp.async.cg.shared.global [%0], [%1], 16;" :: "r"(dst), "l"(src) : "memory");
}
#define CP_COMMIT() asm volatile("cp.async.commit_group;" ::: "memory")
#define CP_WAIT1()  asm volatile("cp.async.wait_group 1;" ::: "memory")

__device__ __forceinline__ uint32_t pack_h2(float x, float y) {
    __half2 t = __floats2half2_rn(x, y);
    return *reinterpret_cast<uint32_t*>(&t);
}
__device__ __forceinline__ void sts128u(uint32_t addr, uint4 v) {
    asm volatile("st.shared.v4.b32 [%0], {%1,%2,%3,%4};"
                 :: "r"(addr), "r"(v.x), "r"(v.y), "r"(v.z), "r"(v.w) : "memory");
}

// ============================ Kernel 1: linear via fp16 mma (64 rows/CTA) ============================
__global__ void __launch_bounds__(256) k_linear(const float* __restrict__ x,
                                                const float* __restrict__ W) {
    extern __shared__ char lsm[];
    const uint32_t sb = smem_u32(lsm);
    const uint32_t xa = sb;                 // 64 x LRS
    const uint32_t Ws = sb + L_TILE_X;      // 128 x LRS
    const int tid = threadIdx.x;
    const int n0 = blockIdx.x * 64;

    #pragma unroll
    for (int l = 0; l < 8; l++) {
        const int f = tid + 256 * l;        // 0..2047
        const int r = f >> 5, c4 = f & 31;
        const float4 v = *(const float4*)(x + (size_t)(n0 + r) * C + c4 * 4);
        uint2 pk; pk.x = pack_h2(v.x, v.y); pk.y = pack_h2(v.z, v.w);
        *(uint2*)(lsm + r * LRS + c4 * 8) = pk;
    }
    #pragma unroll
    for (int l = 0; l < 16; l++) {
        const int f = tid + 256 * l;        // 0..4095
        const int r = f >> 5, c4 = f & 31;
        const float4 v = *(const float4*)(W + (size_t)r * C + c4 * 4);
        uint2 pk; pk.x = pack_h2(v.x, v.y); pk.y = pack_h2(v.z, v.w);
        *(uint2*)(lsm + L_TILE_X + r * LRS + c4 * 8) = pk;
    }
    __syncthreads();

    const int wid = tid >> 5, lid = tid & 31;
    const int wm = wid >> 1, wn = wid & 1;

    const uint32_t aBase = xa + (uint32_t)(wm * 16) * LRS +
                           (uint32_t)((lid & 15) * LRS + ((lid >> 4) << 4));
    const uint32_t bBase = Ws + (uint32_t)((wn * 64 + (lid & 7)) * LRS +
                           (((lid >> 3) & 1) << 4));

    float acc[8][4];
    #pragma unroll
    for (int n = 0; n < 8; n++)
        #pragma unroll
        for (int q = 0; q < 4; q++) acc[n][q] = 0.0f;

    #pragma unroll
    for (int ks = 0; ks < 8; ks++) {
        uint32_t a[4], b[8][2];
        ldsm4(a, aBase + ks * 32);
        #pragma unroll
        for (int n = 0; n < 8; n++)
            ldsm2(b[n], bBase + (uint32_t)(n * 8) * LRS + ks * 32);
        #pragma unroll
        for (int n = 0; n < 8; n++)
            mma_f16(acc[n], a, b[n]);
    }

    const int g = lid >> 2;
    const int c0 = (lid & 3) * 2;
    #pragma unroll
    for (int half = 0; half < 2; half++) {
        const int row = n0 + wm * 16 + g + half * 8;
        #pragma unroll
        for (int n = 0; n < 8; n++) {
            const int col = wn * 64 + n * 8 + c0;
            *(uint32_t*)(g_hf + (size_t)row * C + col) =
                pack_h2(acc[n][half * 2 + 0], acc[n][half * 2 + 1]);
        }
    }
}

// ============================ Kernel 2: fp16 mma.sync SpMM (R6 pipeline, x4t B loads) ============================
__global__ void __launch_bounds__(THREADS, 2)
k_spmm(const float* __restrict__ adj, const float* __restrict__ mask) {
    extern __shared__ char smem[];
    const uint32_t sb = (smem_u32(smem) + 127) & ~127u;

    const int tid = threadIdx.x, wid = tid >> 5, lid = tid & 31;
    const int i0 = blockIdx.x * BM;
    const int k0 = blockIdx.y * KRANGE;

    // ---- A: row = tid>>2 (0..63), kq = (tid&3)*16 floats, 4 float4 each ----
    const int r0 = tid >> 2;
    const int kq = (tid & 3) * 16;
    const float* pa = adj  + (size_t)(i0 + r0) * NROWS + k0 + kq;
    const float* pm = mask + (size_t)(i0 + r0) * NROWS + k0 + kq;
    const uint32_t asoB = (uint32_t)(r0 * RS_A + (tid & 3) * 32);   // bytes

    // ---- B cp.async: brow = tid>>2 (0..63) ----
    const int brow = tid >> 2;
    const __half* pb = g_hf + (size_t)(k0 + brow) * C + (tid & 3) * 16;
    const uint32_t bsoB = (uint32_t)(brow * RS_B + (tid & 3) * 32);

    // ---- warp tile: 32(m) x 32(n) ----
    const int m_base = (wid & 1) * 32;
    const int n_base = (wid >> 1) * 32;
    const uint32_t lane_off_A  = (uint32_t)((lid & 15) * RS_A + ((lid >> 4) << 4));
    // x4 trans: lanes 0-15 -> n-block0, lanes 16-31 -> n-block1 (+16B = +8 cols)
    const uint32_t lane_off_B4 = (uint32_t)((lid & 15) * RS_B + ((lid >> 4) << 4));

    float acc[2][4][4];
    #pragma unroll
    for (int m = 0; m < 2; m++)
        #pragma unroll
        for (int n = 0; n < 4; n++)
            #pragma unroll
            for (int q = 0; q < 4; q++) acc[m][n][q] = 0.0f;

    float4 va[4], vm[4];

    auto loadA = [&](int it) {
        const size_t ofs = (size_t)it * BK;
        #pragma unroll
        for (int j = 0; j < 4; j++) {
            va[j] = *(const float4*)(pa + ofs + j * 4);
            vm[j] = *(const float4*)(pm + ofs + j * 4);
        }
    };
    auto storeA = [&](int stage) {
        const uint32_t dst = sb + (uint32_t)stage * TILE_A + asoB;
        uint4 w0, w1;
        {
            float4 p0, p1;
            p0.x = va[0].x * vm[0].x; p0.y = va[0].y * vm[0].y;
            p0.z = va[0].z * vm[0].z; p0.w = va[0].w * vm[0].w;
            p1.x = va[1].x * vm[1].x; p1.y = va[1].y * vm[1].y;
            p1.z = va[1].z * vm[1].z; p1.w = va[1].w * vm[1].w;
            w0.x = pack_h2(p0.x, p0.y); w0.y = pack_h2(p0.z, p0.w);
            w0.z = pack_h2(p1.x, p1.y); w0.w = pack_h2(p1.z, p1.w);
        }
        {
            float4 p0, p1;
            p0.x = va[2].x * vm[2].x; p0.y = va[2].y * vm[2].y;
            p0.z = va[2].z * vm[2].z; p0.w = va[2].w * vm[2].w;
            p1.x = va[3].x * vm[3].x; p1.y = va[3].y * vm[3].y;
            p1.z = va[3].z * vm[3].z; p1.w = va[3].w * vm[3].w;
            w1.x = pack_h2(p0.x, p0.y); w1.y = pack_h2(p0.z, p0.w);
            w1.z = pack_h2(p1.x, p1.y); w1.w = pack_h2(p1.z, p1.w);
        }
        sts128u(dst, w0);
        sts128u(dst + 16, w1);
    };
    auto cpB = [&](int it, int stage) {
        const uint32_t stB = sb + OFF_B0 + (uint32_t)stage * TILE_BT + bsoB;
        const __half* src = pb + (size_t)it * BK * C;
        cp16(stB,       src);
        cp16(stB + 16,  src + 8);
        cp16(stB + 128, src + 64);
        cp16(stB + 144, src + 72);
    };

    // ---------- prologue (R6) ----------
    loadA(0);
    cpB(0, 0); CP_COMMIT();
    storeA(0);
    loadA(1);
    cpB(1, 1); CP_COMMIT();
    CP_WAIT1();
    __syncthreads();

    int bs2 = 2, bsc = 0;

    // ---------- mainloop (R6) ----------
    #pragma unroll 1
    for (int it = 0; it < NITER; it++) {
        if (it + 2 < NITER) cpB(it + 2, bs2);
        CP_COMMIT();
        if (it + 1 < NITER) storeA((it + 1) & 1);
        if (it + 2 < NITER) loadA(it + 2);

        const uint32_t aB = sb + (uint32_t)(it & 1) * TILE_A +
                            (uint32_t)(m_base * RS_A) + lane_off_A;
        const uint32_t bB = sb + OFF_B0 + (uint32_t)bsc * TILE_BT +
                            (uint32_t)(n_base * 2) + lane_off_B4;

        #pragma unroll
        for (int ks = 0; ks < 4; ks++) {
            uint32_t ah[2][4], bh[4][2];
            #pragma unroll
            for (int m = 0; m < 2; m++)
                ldsm4(ah[m], aB + m * (16 * RS_A) + ks * 32);
            #pragma unroll
            for (int n2 = 0; n2 < 2; n2++) {
                uint32_t q[4];
                ldsm4t(q, bB + (uint32_t)(ks * 16 * RS_B) + (uint32_t)(n2 * 32));
                bh[n2 * 2 + 0][0] = q[0]; bh[n2 * 2 + 0][1] = q[1];
                bh[n2 * 2 + 1][0] = q[2]; bh[n2 * 2 + 1][1] = q[3];
            }
            #pragma unroll
            for (int m = 0; m < 2; m++)
                #pragma unroll
                for (int n = 0; n < 4; n++)
                    mma_f16(acc[m][n], ah[m], bh[n]);
        }

        CP_WAIT1();
        __syncthreads();

        bs2 = (bs2 == 2) ? 0 : bs2 + 1;
        bsc = (bsc == 2) ? 0 : bsc + 1;
    }

    // ---------- epilogue: +I fold (split 0), pack fp16 partials ----------
    {
        const int g = lid >> 2;
        const int c0 = (lid & 3) * 2;
        const bool addI = (blockIdx.y == 0);
        __half* base = g_part + ((size_t)blockIdx.y * NROWS + i0) * C;
        #pragma unroll
        for (int m = 0; m < 2; m++) {
            const int row0 = m_base + m * 16 + g;
            #pragma unroll
            for (int n = 0; n < 4; n++) {
                const int col = n_base + n * 8 + c0;
                float2 v0 = make_float2(acc[m][n][0], acc[m][n][1]);
                float2 v1 = make_float2(acc[m][n][2], acc[m][n][3]);
                if (addI) {
                    const uint32_t h0 =
                        *(const uint32_t*)(g_hf + (size_t)(i0 + row0) * C + col);
                    const uint32_t h1 =
                        *(const uint32_t*)(g_hf + (size_t)(i0 + row0 + 8) * C + col);
                    const __half2 hh0 = *reinterpret_cast<const __half2*>(&h0);
                    const __half2 hh1 = *reinterpret_cast<const __half2*>(&h1);
                    v0.x += __low2float(hh0); v0.y += __high2float(hh0);
                    v1.x += __low2float(hh1); v1.y += __high2float(hh1);
                }
                *(uint32_t*)(base + (size_t)row0 * C + col)       = pack_h2(v0.x, v0.y);
                *(uint32_t*)(base + (size_t)(row0 + 8) * C + col) = pack_h2(v1.x, v1.y);
            }
        }
    }
}

// ============================ Kernel 3: reduce fp16 partials (2 groups/thread) ============================
__global__ void __launch_bounds__(256) k_reduce(float* __restrict__ out) {
    const size_t i0 = (size_t)blockIdx.x * 512 + threadIdx.x;  // group indices i0, i0+256
    float4 s0 = make_float4(0.f, 0.f, 0.f, 0.f);
    float4 s1 = make_float4(0.f, 0.f, 0.f, 0.f);
    #pragma unroll
    for (int p = 0; p < KSPLIT; p++) {
        const size_t base = (size_t)p * (NROWS * C / 4);
        const uint2 a = ((const uint2*)g_part)[base + i0];
        const uint2 b = ((const uint2*)g_part)[base + i0 + 256];
        const __half2 a0 = *reinterpret_cast<const __half2*>(&a.x);
        const __half2 a1 = *reinterpret_cast<const __half2*>(&a.y);
        const __half2 b0 = *reinterpret_cast<const __half2*>(&b.x);
        const __half2 b1 = *reinterpret_cast<const __half2*>(&b.y);
        s0.x += __low2float(a0); s0.y += __high2float(a0);
        s0.z += __low2float(a1); s0.w += __high2float(a1);
        s1.x += __low2float(b0); s1.y += __high2float(b0);
        s1.z += __low2float(b1); s1.w += __high2float(b1);
    }
    ((float4*)out)[i0]       = s0;
    ((float4*)out)[i0 + 256] = s1;
}

// ============================ launch ============================
extern "C" void kernel_launch(void* const* d_in, const int* in_sizes, int n_in,
                              void* d_out, int out_size) {
    const float* x    = (const float*)d_in[0];
    const float* adj  = (const float*)d_in[1];
    const float* mask = (const float*)d_in[2];
    const float* W    = (const float*)d_in[3];
    float* out = (float*)d_out;

    cudaFuncSetAttribute(k_spmm, cudaFuncAttributeMaxDynamicSharedMemorySize, SMEM_BYTES);
    cudaFuncSetAttribute(k_linear, cudaFuncAttributeMaxDynamicSharedMemorySize, L_SMEM);

    k_linear<<<NROWS / 64, 256, L_SMEM>>>(x, W);

    dim3 g2(NROWS / BM, KSPLIT);
    k_spmm<<<g2, THREADS, SMEM_BYTES>>>(adj, mask);

    k_reduce<<<NROWS * C / 4 / 512, 256>>>(out);
}

// round 17
// speedup vs baseline: 1.0480x; 1.0480x over previous
#include <cuda_runtime.h>
#include <cuda_fp16.h>
#include <cstdint>

#define NROWS 8192
#define C     128
#define KSPLIT 8
#define KRANGE (NROWS / KSPLIT)   // 1024
#define BK 64
#define NITER (KRANGE / BK)       // 16
#define BM 64
#define THREADS 256

#define RS_A 144                  // 64 fp16 = 128B + 16B pad
#define RS_B 272                  // 128 fp16 = 256B + 16B pad
#define TILE_A  (BM * RS_A)       // 9216
#define TILE_BT (BK * RS_B)       // 17408
#define OFF_B0  (2 * TILE_A)      // 18432
#define SMEM_BYTES (OFF_B0 + 3 * TILE_BT + 128)   // ~70.8KB -> 2 CTAs/SM

// k_linear smem (64 rows per CTA)
#define LRS 272                   // 128 fp16 + 16B pad
#define L_TILE_X (64 * LRS)       // 17408
#define L_SMEM (L_TILE_X + 128 * LRS + 128)       // ~52.4KB

// ---- scratch ----
__device__ __half g_hf[NROWS * C];            // h fp16 row-major
__device__ __half g_part[KSPLIT * NROWS * C]; // fp16 partials (16 MB)

// ============================ helpers ============================
__device__ __forceinline__ uint32_t smem_u32(const void* p) {
    uint32_t a;
    asm("{ .reg .u64 t; cvta.to.shared.u64 t, %1; cvt.u32.u64 %0, t; }" : "=r"(a) : "l"(p));
    return a;
}
__device__ __forceinline__ void ldsm4(uint32_t* r, uint32_t addr) {
    asm volatile("ldmatrix.sync.aligned.m8n8.x4.shared.b16 {%0,%1,%2,%3}, [%4];"
                 : "=r"(r[0]), "=r"(r[1]), "=r"(r[2]), "=r"(r[3]) : "r"(addr));
}
__device__ __forceinline__ void ldsm2(uint32_t* r, uint32_t addr) {
    asm volatile("ldmatrix.sync.aligned.m8n8.x2.shared.b16 {%0,%1}, [%2];"
                 : "=r"(r[0]), "=r"(r[1]) : "r"(addr));
}
__device__ __forceinline__ void ldsm2t(uint32_t* r, uint32_t addr) {
    asm volatile("ldmatrix.sync.aligned.m8n8.x2.trans.shared.b16 {%0,%1}, [%2];"
                 : "=r"(r[0]), "=r"(r[1]) : "r"(addr));
}
__device__ __forceinline__ void mma_f16(float* d, const uint32_t* a, const uint32_t* b) {
    asm volatile(
        "mma.sync.aligned.m16n8k16.row.col.f32.f16.f16.f32 "
        "{%0,%1,%2,%3}, {%4,%5,%6,%7}, {%8,%9}, {%0,%1,%2,%3};"
        : "+f"(d[0]), "+f"(d[1]), "+f"(d[2]), "+f"(d[3])
        : "r"(a[0]), "r"(a[1]), "r"(a[2]), "r"(a[3]), "r"(b[0]), "r"(b[1]));
}
__device__ __forceinline__ void cp16(uint32_t dst, const void* src) {
    asm volatile("cp.async.cg.shared.global [%0], [%1], 16;" :: "r"(dst), "l"(src) : "memory");
}
#define CP_COMMIT() asm volatile("cp.async.commit_group;" ::: "memory")
#define CP_WAIT1()  asm volatile("cp.async.wait_group 1;" ::: "memory")

__device__ __forceinline__ uint32_t pack_h2(float x, float y) {
    __half2 t = __floats2half2_rn(x, y);
    return *reinterpret_cast<uint32_t*>(&t);
}
__device__ __forceinline__ void sts128u(uint32_t addr, uint4 v) {
    asm volatile("st.shared.v4.b32 [%0], {%1,%2,%3,%4};"
                 :: "r"(addr), "r"(v.x), "r"(v.y), "r"(v.z), "r"(v.w) : "memory");
}

// ============================ Kernel 1: linear via fp16 mma (64 rows/CTA) ============================
__global__ void __launch_bounds__(256) k_linear(const float* __restrict__ x,
                                                const float* __restrict__ W) {
    extern __shared__ char lsm[];
    const uint32_t sb = smem_u32(lsm);
    const uint32_t xa = sb;                 // 64 x LRS
    const uint32_t Ws = sb + L_TILE_X;      // 128 x LRS
    const int tid = threadIdx.x;
    const int n0 = blockIdx.x * 64;

    #pragma unroll
    for (int l = 0; l < 8; l++) {
        const int f = tid + 256 * l;        // 0..2047
        const int r = f >> 5, c4 = f & 31;
        const float4 v = *(const float4*)(x + (size_t)(n0 + r) * C + c4 * 4);
        uint2 pk; pk.x = pack_h2(v.x, v.y); pk.y = pack_h2(v.z, v.w);
        *(uint2*)(lsm + r * LRS + c4 * 8) = pk;
    }
    #pragma unroll
    for (int l = 0; l < 16; l++) {
        const int f = tid + 256 * l;        // 0..4095
        const int r = f >> 5, c4 = f & 31;
        const float4 v = *(const float4*)(W + (size_t)r * C + c4 * 4);
        uint2 pk; pk.x = pack_h2(v.x, v.y); pk.y = pack_h2(v.z, v.w);
        *(uint2*)(lsm + L_TILE_X + r * LRS + c4 * 8) = pk;
    }
    __syncthreads();

    const int wid = tid >> 5, lid = tid & 31;
    const int wm = wid >> 1, wn = wid & 1;

    const uint32_t aBase = xa + (uint32_t)(wm * 16) * LRS +
                           (uint32_t)((lid & 15) * LRS + ((lid >> 4) << 4));
    const uint32_t bBase = Ws + (uint32_t)((wn * 64 + (lid & 7)) * LRS +
                           (((lid >> 3) & 1) << 4));

    float acc[8][4];
    #pragma unroll
    for (int n = 0; n < 8; n++)
        #pragma unroll
        for (int q = 0; q < 4; q++) acc[n][q] = 0.0f;

    #pragma unroll
    for (int ks = 0; ks < 8; ks++) {
        uint32_t a[4], b[8][2];
        ldsm4(a, aBase + ks * 32);
        #pragma unroll
        for (int n = 0; n < 8; n++)
            ldsm2(b[n], bBase + (uint32_t)(n * 8) * LRS + ks * 32);
        #pragma unroll
        for (int n = 0; n < 8; n++)
            mma_f16(acc[n], a, b[n]);
    }

    const int g = lid >> 2;
    const int c0 = (lid & 3) * 2;
    #pragma unroll
    for (int half = 0; half < 2; half++) {
        const int row = n0 + wm * 16 + g + half * 8;
        #pragma unroll
        for (int n = 0; n < 8; n++) {
            const int col = wn * 64 + n * 8 + c0;
            *(uint32_t*)(g_hf + (size_t)row * C + col) =
                pack_h2(acc[n][half * 2 + 0], acc[n][half * 2 + 1]);
        }
    }
}

// ============================ Kernel 2: fp16 mma.sync SpMM (R6 pipeline, plain loads) ============================
__global__ void __launch_bounds__(THREADS, 2)
k_spmm(const float* __restrict__ adj, const float* __restrict__ mask) {
    extern __shared__ char smem[];
    const uint32_t sb = (smem_u32(smem) + 127) & ~127u;

    const int tid = threadIdx.x, wid = tid >> 5, lid = tid & 31;
    const int i0 = blockIdx.x * BM;
    const int k0 = blockIdx.y * KRANGE;

    // ---- A: row = tid>>2 (0..63), kq = (tid&3)*16 floats, 4 float4 each ----
    const int r0 = tid >> 2;
    const int kq = (tid & 3) * 16;
    const float* pa = adj  + (size_t)(i0 + r0) * NROWS + k0 + kq;
    const float* pm = mask + (size_t)(i0 + r0) * NROWS + k0 + kq;
    const uint32_t asoB = (uint32_t)(r0 * RS_A + (tid & 3) * 32);   // bytes

    // ---- B cp.async: brow = tid>>2 (0..63) ----
    const int brow = tid >> 2;
    const __half* pb = g_hf + (size_t)(k0 + brow) * C + (tid & 3) * 16;
    const uint32_t bsoB = (uint32_t)(brow * RS_B + (tid & 3) * 32);

    // ---- warp tile: 32(m) x 32(n) ----
    const int m_base = (wid & 1) * 32;
    const int n_base = (wid >> 1) * 32;
    const uint32_t lane_off_A = (uint32_t)((lid & 15) * RS_A + ((lid >> 4) << 4));
    const uint32_t lane_off_B = (uint32_t)((lid & 15) * RS_B);

    float acc[2][4][4];
    #pragma unroll
    for (int m = 0; m < 2; m++)
        #pragma unroll
        for (int n = 0; n < 4; n++)
            #pragma unroll
            for (int q = 0; q < 4; q++) acc[m][n][q] = 0.0f;

    float4 va[4], vm[4];

    auto loadA = [&](int it) {
        const size_t ofs = (size_t)it * BK;
        #pragma unroll
        for (int j = 0; j < 4; j++) {
            va[j] = *(const float4*)(pa + ofs + j * 4);
            vm[j] = *(const float4*)(pm + ofs + j * 4);
        }
    };
    auto storeA = [&](int stage) {
        const uint32_t dst = sb + (uint32_t)stage * TILE_A + asoB;
        uint4 w0, w1;
        {
            float4 p0, p1;
            p0.x = va[0].x * vm[0].x; p0.y = va[0].y * vm[0].y;
            p0.z = va[0].z * vm[0].z; p0.w = va[0].w * vm[0].w;
            p1.x = va[1].x * vm[1].x; p1.y = va[1].y * vm[1].y;
            p1.z = va[1].z * vm[1].z; p1.w = va[1].w * vm[1].w;
            w0.x = pack_h2(p0.x, p0.y); w0.y = pack_h2(p0.z, p0.w);
            w0.z = pack_h2(p1.x, p1.y); w0.w = pack_h2(p1.z, p1.w);
        }
        {
            float4 p0, p1;
            p0.x = va[2].x * vm[2].x; p0.y = va[2].y * vm[2].y;
            p0.z = va[2].z * vm[2].z; p0.w = va[2].w * vm[2].w;
            p1.x = va[3].x * vm[3].x; p1.y = va[3].y * vm[3].y;
            p1.z = va[3].z * vm[3].z; p1.w = va[3].w * vm[3].w;
            w1.x = pack_h2(p0.x, p0.y); w1.y = pack_h2(p0.z, p0.w);
            w1.z = pack_h2(p1.x, p1.y); w1.w = pack_h2(p1.z, p1.w);
        }
        sts128u(dst, w0);
        sts128u(dst + 16, w1);
    };
    auto cpB = [&](int it, int stage) {
        const uint32_t stB = sb + OFF_B0 + (uint32_t)stage * TILE_BT + bsoB;
        const __half* src = pb + (size_t)it * BK * C;
        cp16(stB,       src);
        cp16(stB + 16,  src + 8);
        cp16(stB + 128, src + 64);
        cp16(stB + 144, src + 72);
    };

    // ---------- prologue (R6) ----------
    loadA(0);
    cpB(0, 0); CP_COMMIT();
    storeA(0);
    loadA(1);
    cpB(1, 1); CP_COMMIT();
    CP_WAIT1();
    __syncthreads();

    int bs2 = 2, bsc = 0;

    // ---------- mainloop (R6) ----------
    #pragma unroll 1
    for (int it = 0; it < NITER; it++) {
        if (it + 2 < NITER) cpB(it + 2, bs2);
        CP_COMMIT();
        if (it + 1 < NITER) storeA((it + 1) & 1);
        if (it + 2 < NITER) loadA(it + 2);

        const uint32_t aB = sb + (uint32_t)(it & 1) * TILE_A +
                            (uint32_t)(m_base * RS_A) + lane_off_A;
        const uint32_t bB = sb + OFF_B0 + (uint32_t)bsc * TILE_BT + lane_off_B;

        #pragma unroll
        for (int ks = 0; ks < 4; ks++) {
            uint32_t ah[2][4], bh[4][2];
            #pragma unroll
            for (int m = 0; m < 2; m++)
                ldsm4(ah[m], aB + m * (16 * RS_A) + ks * 32);
            #pragma unroll
            for (int n = 0; n < 4; n++)
                ldsm2t(bh[n], bB + (uint32_t)(ks * 16 * RS_B) +
                              (uint32_t)((n_base + n * 8) * 2));
            #pragma unroll
            for (int m = 0; m < 2; m++)
                #pragma unroll
                for (int n = 0; n < 4; n++)
                    mma_f16(acc[m][n], ah[m], bh[n]);
        }

        CP_WAIT1();
        __syncthreads();

        bs2 = (bs2 == 2) ? 0 : bs2 + 1;
        bsc = (bsc == 2) ? 0 : bsc + 1;
    }

    // ---------- epilogue: +I fold (split 0), pack fp16 partials ----------
    {
        const int g = lid >> 2;
        const int c0 = (lid & 3) * 2;
        const bool addI = (blockIdx.y == 0);
        __half* base = g_part + ((size_t)blockIdx.y * NROWS + i0) * C;
        #pragma unroll
        for (int m = 0; m < 2; m++) {
            const int row0 = m_base + m * 16 + g;
            #pragma unroll
            for (int n = 0; n < 4; n++) {
                const int col = n_base + n * 8 + c0;
                float2 v0 = make_float2(acc[m][n][0], acc[m][n][1]);
                float2 v1 = make_float2(acc[m][n][2], acc[m][n][3]);
                if (addI) {
                    const uint32_t h0 =
                        *(const uint32_t*)(g_hf + (size_t)(i0 + row0) * C + col);
                    const uint32_t h1 =
                        *(const uint32_t*)(g_hf + (size_t)(i0 + row0 + 8) * C + col);
                    const __half2 hh0 = *reinterpret_cast<const __half2*>(&h0);
                    const __half2 hh1 = *reinterpret_cast<const __half2*>(&h1);
                    v0.x += __low2float(hh0); v0.y += __high2float(hh0);
                    v1.x += __low2float(hh1); v1.y += __high2float(hh1);
                }
                *(uint32_t*)(base + (size_t)row0 * C + col)       = pack_h2(v0.x, v0.y);
                *(uint32_t*)(base + (size_t)(row0 + 8) * C + col) = pack_h2(v1.x, v1.y);
            }
        }
    }
}

// ============================ Kernel 3: reduce fp16 partials (2 groups/thread) ============================
__global__ void __launch_bounds__(256) k_reduce(float* __restrict__ out) {
    const size_t i0 = (size_t)blockIdx.x * 512 + threadIdx.x;  // group indices i0, i0+256
    float4 s0 = make_float4(0.f, 0.f, 0.f, 0.f);
    float4 s1 = make_float4(0.f, 0.f, 0.f, 0.f);
    #pragma unroll
    for (int p = 0; p < KSPLIT; p++) {
        const size_t base = (size_t)p * (NROWS * C / 4);
        const uint2 a = ((const uint2*)g_part)[base + i0];
        const uint2 b = ((const uint2*)g_part)[base + i0 + 256];
        const __half2 a0 = *reinterpret_cast<const __half2*>(&a.x);
        const __half2 a1 = *reinterpret_cast<const __half2*>(&a.y);
        const __half2 b0 = *reinterpret_cast<const __half2*>(&b.x);
        const __half2 b1 = *reinterpret_cast<const __half2*>(&b.y);
        s0.x += __low2float(a0); s0.y += __high2float(a0);
        s0.z += __low2float(a1); s0.w += __high2float(a1);
        s1.x += __low2float(b0); s1.y += __high2float(b0);
        s1.z += __low2float(b1); s1.w += __high2float(b1);
    }
    ((float4*)out)[i0]       = s0;
    ((float4*)out)[i0 + 256] = s1;
}

// ============================ launch ============================
extern "C" void kernel_launch(void* const* d_in, const int* in_sizes, int n_in,
                              void* d_out, int out_size) {
    const float* x    = (const float*)d_in[0];
    const float* adj  = (const float*)d_in[1];
    const float* mask = (const float*)d_in[2];
    const float* W    = (const float*)d_in[3];
    float* out = (float*)d_out;

    cudaFuncSetAttribute(k_spmm, cudaFuncAttributeMaxDynamicSharedMemorySize, SMEM_BYTES);
    cudaFuncSetAttribute(k_linear, cudaFuncAttributeMaxDynamicSharedMemorySize, L_SMEM);

    k_linear<<<NROWS / 64, 256, L_SMEM>>>(x, W);

    dim3 g2(NROWS / BM, KSPLIT);
    k_spmm<<<g2, THREADS, SMEM_BYTES>>>(adj, mask);

    k_reduce<<<NROWS * C / 4 / 512, 256>>>(out);
}